// round 16
// baseline (speedup 1.0000x reference)
#include <cuda_runtime.h>
#include <cstdint>

#define NPTS  100000
#define KVOL  27
#define PAIRS 60000
#define CCH   64
#define RPT   128                      // pair rows per tile
#define TPB   11                       // tiles per block (grid 43*27=1161 ~ 3.92 waves of 296)
#define NT128 ((PAIRS + RPT - 1) / RPT)        // 469
#define GX    ((NT128 + TPB - 1) / TPB)        // 43

// smem: sA[2] 128x64 f32-as-tf32 (swizzled 256B rows, 2x32KB) | sB 64x64 tf32
//       (16KB) | W scratch 64x66 f32 (16.9KB) | maps: 3 bufs x (128 in + 128 out)
#define SA_OFF   0
#define SB_OFF   65536
#define WS_OFF   81920
#define MAPS_OFF 98816
#define SMEM_BYTES 101888

#define RED_V4(ptr, x, y, z, w) \
    asm volatile("red.global.add.v4.f32 [%0], {%1,%2,%3,%4};" \
                 :: "l"(ptr), "f"(x), "f"(y), "f"(z), "f"(w) : "memory")

__device__ __forceinline__ uint32_t smem_u32(const void* p) {
    uint32_t a;
    asm("{ .reg .u64 t; cvta.to.shared.u64 t, %1; cvt.u32.u64 %0, t; }"
        : "=r"(a) : "l"(p));
    return a;
}

__device__ __forceinline__ uint32_t f2tf32(float f) {
    uint32_t r;
    asm("cvt.rna.tf32.f32 %0, %1;" : "=r"(r) : "f"(f));
    return r;
}

// .cg: bypass L1 (no reuse in gathered input; keep L1 bandwidth for LDSM/RED)
#define CP_ASYNC16(dst, src, sz) \
    asm volatile("cp.async.cg.shared.global [%0], [%1], 16, %2;" \
                 :: "r"(dst), "l"(src), "r"(sz) : "memory")

#define LDSM_X4(r0, r1, r2, r3, addr) \
    asm volatile("ldmatrix.sync.aligned.m8n8.x4.shared.b16 {%0,%1,%2,%3}, [%4];" \
                 : "=r"(r0), "=r"(r1), "=r"(r2), "=r"(r3) : "r"(addr))

#define MMA_TF32(c, a0, a1, a2, a3, b0, b1) \
    asm volatile("mma.sync.aligned.m16n8k8.row.col.f32.tf32.tf32.f32 " \
                 "{%0,%1,%2,%3}, {%4,%5,%6,%7}, {%8,%9}, {%0,%1,%2,%3};" \
                 : "+f"(c[0]), "+f"(c[1]), "+f"(c[2]), "+f"(c[3]) \
                 : "r"(a0), "r"(a1), "r"(a2), "r"(a3), "r"(b0), "r"(b1))

// vectorized: one float4 per thread, bias row broadcast from registers
__global__ void __launch_bounds__(256) init_bias_kernel(
    const float* __restrict__ bias, float* __restrict__ out)
{
    int idx = blockIdx.x * 256 + threadIdx.x;          // float4 index
    if (idx < NPTS * (CCH / 4)) {
        float4 b = ((const float4*)bias)[idx & (CCH / 4 - 1)];
        ((float4*)out)[idx] = b;
    }
}

// swizzled byte offset inside a 256B row: chunk' = k16 ^ (row & 7)
__device__ __forceinline__ uint32_t sw_off(int row, int k16) {
    return (uint32_t)(row * 256 + ((k16 ^ (row & 7)) << 4));
}

// B-position permutation (involution, per 32-col half):
// logical col n (n5 = n&31) stored at position (n&32) + 8*((n5>>1)&3) + 2*(n5>>3) + (n5&1).
// With this layout the m16n8k8 C-fragment of lane q holds logical cols 8q..8q+7
// of rows Q and Q+8 -> scatter needs NO shuffles.
__device__ __forceinline__ int bperm(int n) {
    int n5 = n & 31;
    return (n & 32) + 8 * ((n5 >> 1) & 3) + 2 * (n5 >> 3) + (n5 & 1);
}

__global__ void __launch_bounds__(256) sparse_conv_kernel(
    const float* __restrict__ input,
    const float* __restrict__ kernel,
    const int*   __restrict__ in_map,
    const int*   __restrict__ out_map,
    float*       __restrict__ out)
{
    extern __shared__ __align__(1024) char smem[];
    const uint32_t sb = smem_u32(smem);
    int* mapsB = (int*)(smem + MAPS_OFF);   // 3 bufs x 256 ints (in[128], out[128])

    const int k    = blockIdx.y;
    const int t0   = blockIdx.x * TPB;      // first 128-pair tile of this block
    const int tid  = threadIdx.x;
    const int w    = tid >> 5;
    const int l    = tid & 31;
    const int band = w >> 1;                // 32-row band
    const int half = w & 1;                 // 32-col half

    // ---- prologue: W LDG + maps(tile0) LDG issued together ----
    float4 wv[4];
    {
        const float4* Wg = (const float4*)(kernel + k * CCH * CCH);
        #pragma unroll
        for (int s = 0; s < 4; s++) wv[s] = Wg[tid + 256 * s];
    }
    int mIn = -1, mOut = -1;
    if (tid < RPT) {
        int pp = t0 * RPT + tid;
        if (pp < PAIRS) {
            mIn  = in_map [k * PAIRS + pp];
            mOut = out_map[k * PAIRS + pp];
        }
    }

    // W -> padded scratch [i][n] (stride 66); maps tile0 -> buf 0
    {
        float* scratch = (float*)(smem + WS_OFF);
        #pragma unroll
        for (int s = 0; s < 4; s++) {
            int e  = tid + 256 * s;
            int i  = e >> 4;
            int o4 = e & 15;
            float* d = scratch + 66 * i + 4 * o4;
            d[0] = wv[s].x; d[1] = wv[s].y; d[2] = wv[s].z; d[3] = wv[s].w;
        }
    }
    if (tid < RPT) {
        mapsB[tid]       = mIn;
        mapsB[RPT + tid] = mOut;
    }
    __syncthreads();

    // issue gather for tile 0 (maps via LDS), then W transpose -> sB
    #pragma unroll
    for (int s = 0; s < 8; s++) {
        int m   = tid + 256 * s;
        int p   = m >> 4;
        int j16 = m & 15;
        int row = mapsB[p];
        uint32_t dst = sb + SA_OFF + sw_off(p, j16);
        const char* src = (const char*)input
                        + (size_t)(row < 0 ? 0 : row) * 256 + j16 * 16;
        CP_ASYNC16(dst, src, row >= 0 ? 16u : 0u);
    }
    asm volatile("cp.async.commit_group;" ::: "memory");

    {
        float* scratch = (float*)(smem + WS_OFF);
        int n   = tid & 63;
        int pos = bperm(n);                   // permuted sB row for logical col n
        int ib  = (tid >> 6) * 16;
        uint32_t tv[16];
        #pragma unroll
        for (int j = 0; j < 16; j++) tv[j] = f2tf32(scratch[66 * (ib + j) + n]);
        #pragma unroll
        for (int c = 0; c < 4; c++) {
            uint4 q4 = make_uint4(tv[4*c], tv[4*c+1], tv[4*c+2], tv[4*c+3]);
            *(uint4*)(smem + SB_OFF + sw_off(pos, (ib >> 2) + c)) = q4;
        }
    }

    // LDG maps for tile 1
    mIn = -1; mOut = -1;
    if (tid < RPT && 1 < TPB) {
        int pp = (t0 + 1) * RPT + tid;
        if (pp < PAIRS) {
            mIn  = in_map [k * PAIRS + pp];
            mOut = out_map[k * PAIRS + pp];
        }
    }

    // GEMM fragment constants
    const int arowB = 32 * band + (((l >> 3) & 1) << 3) + (l & 7);  // + 16*mt
    const int ahi   = l >> 4;
    const int asw   = arowB & 7;
    const int brow  = ((l >> 4) << 3) + (l & 7);                    // + n0
    const int bhi   = (l >> 3) & 1;
    const int bsw   = brow & 7;
    const uint32_t bBase = sb + SB_OFF + brow * 256;
    const int Q = l >> 2;
    const int q = l & 3;

    // ---- hoist ALL B fragments into registers (sB is block-constant) ----
    __syncthreads();                        // sB fully written, block-wide
    uint32_t bf[8][4][2];
    #pragma unroll
    for (int kk = 0; kk < 8; kk++) {
        #pragma unroll
        for (int gl = 0; gl < 2; gl++) {
            int g = 2 * half + gl;
            uint32_t r0, r1, r2, r3;
            uint32_t addr = bBase + g * 4096 + ((((kk << 1) | bhi) ^ bsw) << 4);
            LDSM_X4(r0, r1, r2, r3, addr);
            bf[kk][2 * gl][0] = r0;     bf[kk][2 * gl][1] = r1;
            bf[kk][2 * gl + 1][0] = r2; bf[kk][2 * gl + 1][1] = r3;
        }
    }

    // ---- pipelined tile loop ----
    for (int t = 0; t < TPB; t++) {
        const int cur = t & 1;
        const int mb  = t % 3;
        const int nb  = (t + 1) % 3;

        asm volatile("cp.async.wait_group 0;" ::: "memory");

        // stage maps for tile t+1 (regs loaded last iteration)
        if (t + 1 < TPB && tid < RPT) {
            mapsB[nb * 256 + tid]       = mIn;
            mapsB[nb * 256 + RPT + tid] = mOut;
        }
        __syncthreads();   // sA[cur] ready; maps t+1 visible; sA[cur^1] reads done

        // preload scatter indices for THIS tile (latency hides under GEMM)
        const int* sOutB = mapsB + mb * 256 + RPT;
        int oIdx[2][2];
        #pragma unroll
        for (int mt = 0; mt < 2; mt++)
            #pragma unroll
            for (int h = 0; h < 2; h++)
                oIdx[mt][h] = sOutB[32 * band + 16 * mt + Q + 8 * h];

        // issue gather for tile t+1 into the other buffer
        if (t + 1 < TPB) {
            #pragma unroll
            for (int s = 0; s < 8; s++) {
                int m   = tid + 256 * s;
                int p   = m >> 4;
                int j16 = m & 15;
                int row = mapsB[nb * 256 + p];
                uint32_t dst = sb + SA_OFF + (cur ^ 1) * 32768 + sw_off(p, j16);
                const char* src = (const char*)input
                                + (size_t)(row < 0 ? 0 : row) * 256 + j16 * 16;
                CP_ASYNC16(dst, src, row >= 0 ? 16u : 0u);
            }
            asm volatile("cp.async.commit_group;" ::: "memory");
            // LDG maps for tile t+2
            mIn = -1; mOut = -1;
            if (t + 2 < TPB && tid < RPT) {
                int pp = (t0 + t + 2) * RPT + tid;
                if (pp < PAIRS) {
                    mIn  = in_map [k * PAIRS + pp];
                    mOut = out_map[k * PAIRS + pp];
                }
            }
        }

        // ---- GEMM: warp (band,half) -> rows [32*band,+32) x cols [32*half,+32) ----
        float acc[2][4][4];
        #pragma unroll
        for (int mt = 0; mt < 2; mt++)
            #pragma unroll
            for (int nt = 0; nt < 4; nt++)
                #pragma unroll
                for (int c = 0; c < 4; c++) acc[mt][nt][c] = 0.f;

        const uint32_t aBase = sb + SA_OFF + cur * 32768 + arowB * 256;

        #pragma unroll
        for (int kk = 0; kk < 8; kk++) {
            uint32_t a[2][4];
            #pragma unroll
            for (int mt = 0; mt < 2; mt++) {
                uint32_t addr = aBase + mt * 4096 + ((((kk << 1) | ahi) ^ asw) << 4);
                LDSM_X4(a[mt][0], a[mt][1], a[mt][2], a[mt][3], addr);
            }
            #pragma unroll
            for (int mt = 0; mt < 2; mt++)
                #pragma unroll
                for (int nt = 0; nt < 4; nt++)
                    MMA_TF32(acc[mt][nt], a[mt][0], a[mt][1], a[mt][2], a[mt][3],
                             bf[kk][nt][0], bf[kk][nt][1]);
        }

        // ---- scatter: permuted-B layout -> lane q holds logical cols 8q..8q+7
        // of rows Q and Q+8; two red.v4 per (row,mt), NO shuffles ----
        #pragma unroll
        for (int mt = 0; mt < 2; mt++) {
            #pragma unroll
            for (int h = 0; h < 2; h++) {
                int o = oIdx[mt][h];
                if (o >= 0) {
                    float* dst = out + o * CCH + 32 * half + 8 * q;
                    RED_V4(dst,
                           acc[mt][0][2 * h + 0], acc[mt][0][2 * h + 1],
                           acc[mt][1][2 * h + 0], acc[mt][1][2 * h + 1]);
                    RED_V4(dst + 4,
                           acc[mt][2][2 * h + 0], acc[mt][2][2 * h + 1],
                           acc[mt][3][2 * h + 0], acc[mt][3][2 * h + 1]);
                }
            }
        }
    }
}

extern "C" void kernel_launch(void* const* d_in, const int* in_sizes, int n_in,
                              void* d_out, int out_size)
{
    const float* input  = (const float*)d_in[0];
    const float* kern   = (const float*)d_in[1];
    const float* bias   = (const float*)d_in[2];
    const int*   in_map = (const int*)  d_in[3];
    const int*   out_map= (const int*)  d_in[4];
    float* out = (float*)d_out;

    cudaFuncSetAttribute(sparse_conv_kernel,
                         cudaFuncAttributeMaxDynamicSharedMemorySize, SMEM_BYTES);

    init_bias_kernel<<<(NPTS * (CCH / 4) + 255) / 256, 256>>>(bias, out);

    dim3 grid(GX, KVOL);
    sparse_conv_kernel<<<grid, 256, SMEM_BYTES>>>(input, kern, in_map, out_map, out);
}

// round 17
// speedup vs baseline: 1.7026x; 1.7026x over previous
#include <cuda_runtime.h>
#include <cstdint>

#define NPTS  100000
#define KVOL  27
#define PAIRS 60000
#define CCH   64
#define RPT   128                      // pair rows per tile
#define TPB   11                       // tiles per block (grid 43*27=1161 ~ 3.92 waves of 296)
#define NT128 ((PAIRS + RPT - 1) / RPT)        // 469
#define GX    ((NT128 + TPB - 1) / TPB)        // 43

// smem: sA[2] 128x64 f32-as-tf32 (swizzled 256B rows, 2x32KB) | sB 64x64 tf32
//       (16KB) | W scratch 64x66 f32 (16.9KB) | maps: 3 bufs x (128 in + 128 out)
#define SA_OFF   0
#define SB_OFF   65536
#define WS_OFF   81920
#define MAPS_OFF 98816
#define SMEM_BYTES 101888

#define RED_V4(ptr, x, y, z, w) \
    asm volatile("red.global.add.v4.f32 [%0], {%1,%2,%3,%4};" \
                 :: "l"(ptr), "f"(x), "f"(y), "f"(z), "f"(w) : "memory")

__device__ __forceinline__ uint32_t smem_u32(const void* p) {
    uint32_t a;
    asm("{ .reg .u64 t; cvta.to.shared.u64 t, %1; cvt.u32.u64 %0, t; }"
        : "=r"(a) : "l"(p));
    return a;
}

__device__ __forceinline__ uint32_t f2tf32(float f) {
    uint32_t r;
    asm("cvt.rna.tf32.f32 %0, %1;" : "=r"(r) : "f"(f));
    return r;
}

// .cg: bypass L1 (no reuse in gathered input; keep L1 bandwidth for LDSM/RED)
#define CP_ASYNC16(dst, src, sz) \
    asm volatile("cp.async.cg.shared.global [%0], [%1], 16, %2;" \
                 :: "r"(dst), "l"(src), "r"(sz) : "memory")

#define LDSM_X4(r0, r1, r2, r3, addr) \
    asm volatile("ldmatrix.sync.aligned.m8n8.x4.shared.b16 {%0,%1,%2,%3}, [%4];" \
                 : "=r"(r0), "=r"(r1), "=r"(r2), "=r"(r3) : "r"(addr))

#define MMA_TF32(c, a0, a1, a2, a3, b0, b1) \
    asm volatile("mma.sync.aligned.m16n8k8.row.col.f32.tf32.tf32.f32 " \
                 "{%0,%1,%2,%3}, {%4,%5,%6,%7}, {%8,%9}, {%0,%1,%2,%3};" \
                 : "+f"(c[0]), "+f"(c[1]), "+f"(c[2]), "+f"(c[3]) \
                 : "r"(a0), "r"(a1), "r"(a2), "r"(a3), "r"(b0), "r"(b1))

// vectorized: one float4 per thread, bias row broadcast from registers
__global__ void __launch_bounds__(256) init_bias_kernel(
    const float* __restrict__ bias, float* __restrict__ out)
{
    int idx = blockIdx.x * 256 + threadIdx.x;          // float4 index
    if (idx < NPTS * (CCH / 4)) {
        float4 b = ((const float4*)bias)[idx & (CCH / 4 - 1)];
        ((float4*)out)[idx] = b;
    }
}

// swizzled byte offset inside a 256B row: chunk' = k16 ^ (row & 7)
__device__ __forceinline__ uint32_t sw_off(int row, int k16) {
    return (uint32_t)(row * 256 + ((k16 ^ (row & 7)) << 4));
}

__global__ void __launch_bounds__(256) sparse_conv_kernel(
    const float* __restrict__ input,
    const float* __restrict__ kernel,
    const int*   __restrict__ in_map,
    const int*   __restrict__ out_map,
    float*       __restrict__ out)
{
    extern __shared__ __align__(1024) char smem[];
    const uint32_t sb = smem_u32(smem);
    int* mapsB = (int*)(smem + MAPS_OFF);   // 3 bufs x 256 ints (in[128], out[128])

    const int k    = blockIdx.y;
    const int t0   = blockIdx.x * TPB;      // first 128-pair tile of this block
    const int tid  = threadIdx.x;
    const int w    = tid >> 5;
    const int l    = tid & 31;
    const int band = w >> 1;                // 32-row band
    const int half = w & 1;                 // 32-col half

    // ---- prologue: W LDG + maps(tile0) LDG issued together ----
    float4 wv[4];
    {
        const float4* Wg = (const float4*)(kernel + k * CCH * CCH);
        #pragma unroll
        for (int s = 0; s < 4; s++) wv[s] = Wg[tid + 256 * s];
    }
    int mIn = -1, mOut = -1;
    if (tid < RPT) {
        int pp = t0 * RPT + tid;
        if (pp < PAIRS) {
            mIn  = in_map [k * PAIRS + pp];
            mOut = out_map[k * PAIRS + pp];
        }
    }

    // W -> padded scratch [i][n] (stride 66); maps tile0 -> buf 0
    {
        float* scratch = (float*)(smem + WS_OFF);
        #pragma unroll
        for (int s = 0; s < 4; s++) {
            int e  = tid + 256 * s;
            int i  = e >> 4;
            int o4 = e & 15;
            float* d = scratch + 66 * i + 4 * o4;
            d[0] = wv[s].x; d[1] = wv[s].y; d[2] = wv[s].z; d[3] = wv[s].w;
        }
    }
    if (tid < RPT) {
        mapsB[tid]       = mIn;
        mapsB[RPT + tid] = mOut;
    }
    __syncthreads();

    // issue gather for tile 0 (maps via LDS), then W transpose -> sB
    #pragma unroll
    for (int s = 0; s < 8; s++) {
        int m   = tid + 256 * s;
        int p   = m >> 4;
        int j16 = m & 15;
        int row = mapsB[p];
        uint32_t dst = sb + SA_OFF + sw_off(p, j16);
        const char* src = (const char*)input
                        + (size_t)(row < 0 ? 0 : row) * 256 + j16 * 16;
        CP_ASYNC16(dst, src, row >= 0 ? 16u : 0u);
    }
    asm volatile("cp.async.commit_group;" ::: "memory");

    {
        float* scratch = (float*)(smem + WS_OFF);
        int n  = tid & 63;
        int ib = (tid >> 6) * 16;
        uint32_t tv[16];
        #pragma unroll
        for (int j = 0; j < 16; j++) tv[j] = f2tf32(scratch[66 * (ib + j) + n]);
        #pragma unroll
        for (int c = 0; c < 4; c++) {
            uint4 q4 = make_uint4(tv[4*c], tv[4*c+1], tv[4*c+2], tv[4*c+3]);
            *(uint4*)(smem + SB_OFF + sw_off(n, (ib >> 2) + c)) = q4;
        }
    }

    // LDG maps for tile 1
    mIn = -1; mOut = -1;
    if (tid < RPT && 1 < TPB) {
        int pp = (t0 + 1) * RPT + tid;
        if (pp < PAIRS) {
            mIn  = in_map [k * PAIRS + pp];
            mOut = out_map[k * PAIRS + pp];
        }
    }

    // GEMM fragment constants
    const int arowB = 32 * band + (((l >> 3) & 1) << 3) + (l & 7);  // + 16*mt
    const int ahi   = l >> 4;
    const int asw   = arowB & 7;
    const int brow  = ((l >> 4) << 3) + (l & 7);                    // + n0
    const int bhi   = (l >> 3) & 1;
    const int bsw   = brow & 7;
    const uint32_t bBase = sb + SB_OFF + brow * 256;
    const int Q = l >> 2;
    const int q = l & 3;

    // ---- hoist ALL B fragments into registers (sB is block-constant) ----
    __syncthreads();                        // sB fully written, block-wide
    uint32_t bf[8][4][2];
    #pragma unroll
    for (int kk = 0; kk < 8; kk++) {
        #pragma unroll
        for (int gl = 0; gl < 2; gl++) {
            int g = 2 * half + gl;
            uint32_t r0, r1, r2, r3;
            uint32_t addr = bBase + g * 4096 + ((((kk << 1) | bhi) ^ bsw) << 4);
            LDSM_X4(r0, r1, r2, r3, addr);
            bf[kk][2 * gl][0] = r0;     bf[kk][2 * gl][1] = r1;
            bf[kk][2 * gl + 1][0] = r2; bf[kk][2 * gl + 1][1] = r3;
        }
    }

    // ---- pipelined tile loop ----
    for (int t = 0; t < TPB; t++) {
        const int cur = t & 1;
        const int mb  = t % 3;
        const int nb  = (t + 1) % 3;

        asm volatile("cp.async.wait_group 0;" ::: "memory");

        // stage maps for tile t+1 (regs loaded last iteration)
        if (t + 1 < TPB && tid < RPT) {
            mapsB[nb * 256 + tid]       = mIn;
            mapsB[nb * 256 + RPT + tid] = mOut;
        }
        __syncthreads();   // sA[cur] ready; maps t+1 visible; sA[cur^1] reads done

        // issue gather for tile t+1 FIRST (requests leave earliest)
        if (t + 1 < TPB) {
            #pragma unroll
            for (int s = 0; s < 8; s++) {
                int m   = tid + 256 * s;
                int p   = m >> 4;
                int j16 = m & 15;
                int row = mapsB[nb * 256 + p];
                uint32_t dst = sb + SA_OFF + (cur ^ 1) * 32768 + sw_off(p, j16);
                const char* src = (const char*)input
                                + (size_t)(row < 0 ? 0 : row) * 256 + j16 * 16;
                CP_ASYNC16(dst, src, row >= 0 ? 16u : 0u);
            }
            asm volatile("cp.async.commit_group;" ::: "memory");
        }

        // preload scatter indices for THIS tile (latency hides under GEMM)
        const int* sOutB = mapsB + mb * 256 + RPT;
        int oIdx[2][2];
        #pragma unroll
        for (int mt = 0; mt < 2; mt++)
            #pragma unroll
            for (int h = 0; h < 2; h++)
                oIdx[mt][h] = sOutB[32 * band + 16 * mt + Q + 8 * h];

        // LDG maps for tile t+2
        if (t + 1 < TPB) {
            mIn = -1; mOut = -1;
            if (t + 2 < TPB && tid < RPT) {
                int pp = (t0 + t + 2) * RPT + tid;
                if (pp < PAIRS) {
                    mIn  = in_map [k * PAIRS + pp];
                    mOut = out_map[k * PAIRS + pp];
                }
            }
        }

        // ---- GEMM: warp (band,half) -> rows [32*band,+32) x cols [32*half,+32) ----
        float acc[2][4][4];
        #pragma unroll
        for (int mt = 0; mt < 2; mt++)
            #pragma unroll
            for (int nt = 0; nt < 4; nt++)
                #pragma unroll
                for (int c = 0; c < 4; c++) acc[mt][nt][c] = 0.f;

        const uint32_t aBase = sb + SA_OFF + cur * 32768 + arowB * 256;

        #pragma unroll
        for (int kk = 0; kk < 8; kk++) {
            uint32_t a[2][4];
            #pragma unroll
            for (int mt = 0; mt < 2; mt++) {
                uint32_t addr = aBase + mt * 4096 + ((((kk << 1) | ahi) ^ asw) << 4);
                LDSM_X4(a[mt][0], a[mt][1], a[mt][2], a[mt][3], addr);
            }
            #pragma unroll
            for (int mt = 0; mt < 2; mt++)
                #pragma unroll
                for (int nt = 0; nt < 4; nt++)
                    MMA_TF32(acc[mt][nt], a[mt][0], a[mt][1], a[mt][2], a[mt][3],
                             bf[kk][nt][0], bf[kk][nt][1]);
        }

        // ---- scatter: intra-quad regroup -> each red.v4 touches 8 rows ----
        #pragma unroll
        for (int mt = 0; mt < 2; mt++) {
            #pragma unroll
            for (int h = 0; h < 2; h++) {
                int o = oIdx[mt][h];
                #pragma unroll
                for (int x = 0; x < 2; x++) {
                    float v[4];
                    #pragma unroll
                    for (int j = 0; j < 4; j++) {
                        int par  = j & 1;
                        int srcl = (l & ~3) + 2 * (q & 1) + (j >> 1);
                        float s0 = __shfl_sync(0xffffffffu,
                                               acc[mt][2 * x + 0][2 * h + par], srcl);
                        float s1 = __shfl_sync(0xffffffffu,
                                               acc[mt][2 * x + 1][2 * h + par], srcl);
                        v[j] = (q >> 1) ? s1 : s0;
                    }
                    if (o >= 0)
                        RED_V4(out + o * CCH + 32 * half + 16 * x + 4 * q,
                               v[0], v[1], v[2], v[3]);
                }
            }
        }
    }
}

extern "C" void kernel_launch(void* const* d_in, const int* in_sizes, int n_in,
                              void* d_out, int out_size)
{
    const float* input  = (const float*)d_in[0];
    const float* kern   = (const float*)d_in[1];
    const float* bias   = (const float*)d_in[2];
    const int*   in_map = (const int*)  d_in[3];
    const int*   out_map= (const int*)  d_in[4];
    float* out = (float*)d_out;

    cudaFuncSetAttribute(sparse_conv_kernel,
                         cudaFuncAttributeMaxDynamicSharedMemorySize, SMEM_BYTES);

    init_bias_kernel<<<(NPTS * (CCH / 4) + 255) / 256, 256>>>(bias, out);

    dim3 grid(GX, KVOL);
    sparse_conv_kernel<<<grid, 256, SMEM_BYTES>>>(input, kern, in_map, out_map, out);
}